// round 1
// baseline (speedup 1.0000x reference)
#include <cuda_runtime.h>
#include <math.h>

// Problem dims
#define SS 512
#define BB 64
#define II 512
#define HH 1024
#define BH (BB*HH)

// Recurrent kernel decomposition
#define NT 16          // N tiles of 64 columns
#define KC 8           // K chunks of 128
#define NB (NT*KC)     // 128 persistent blocks (<= 148 SMs -> single wave)

// -------------------- device scratch (no cudaMalloc allowed) --------------------
__device__ float g_pre[SS*BH];        // V x_t + b_V + b_W, precomputed    (134 MB)
__device__ float g_part[KC][BH];      // split-K partial sums per step     (2 MB)
__device__ unsigned g_bar_cnt = 0;
__device__ volatile unsigned g_bar_gen = 0;

// -------------------- software grid barrier (sense via generation) --------------
__device__ __forceinline__ void grid_sync_128() {
    __syncthreads();
    __threadfence();                       // publish our STGs to L2 before arrival
    if (threadIdx.x == 0) {
        unsigned gen = g_bar_gen;
        unsigned ticket = atomicAdd(&g_bar_cnt, 1u);
        if (ticket == NB - 1u) {
            g_bar_cnt = 0;                 // reset BEFORE releasing
            __threadfence();
            g_bar_gen = gen + 1u;          // release
        } else {
            while (g_bar_gen == gen) { }   // spin (volatile load)
        }
    }
    __syncthreads();
}

// =================================================================================
// Kernel 1: g_pre[s,b,h] = sum_i x[s,b,i]*Vw[h,i] + Vb[h] + Wb[h]
// M = S*B = 32768, N = H = 1024, K = I = 512.  Block tile 64x64, BK=16, 4x4 micro.
// =================================================================================
__global__ void __launch_bounds__(256) pre_gemm_kernel(
        const float* __restrict__ x,
        const float* __restrict__ Vw,
        const float* __restrict__ Wb,
        const float* __restrict__ Vb) {
    __shared__ float As[64][20];   // [m][k], pad 20 -> conflict-free strided reads
    __shared__ float Ws[16][64];   // [k][n] transposed

    const int bm = blockIdx.x;     // 0..511
    const int bn = blockIdx.y;     // 0..15
    const int t  = threadIdx.x;
    const int tx = t & 15;         // n micro
    const int ty = t >> 4;         // m micro

    float c[4][4] = {};

    const float* Arow = x  + (size_t)(bm*64) * II;
    const float* Wrow = Vw + (size_t)(bn*64) * II;

    for (int kb = 0; kb < II; kb += 16) {
        // Load A tile 64x16 and W tile 64x16 (1 float4 each per thread)
        {
            int r  = t >> 2;           // 0..63
            int k4 = (t & 3) << 2;     // 0,4,8,12
            float4 va = *(const float4*)(Arow + (size_t)r*II + kb + k4);
            As[r][k4+0] = va.x; As[r][k4+1] = va.y;
            As[r][k4+2] = va.z; As[r][k4+3] = va.w;
            float4 vw = *(const float4*)(Wrow + (size_t)r*II + kb + k4);
            Ws[k4+0][r] = vw.x; Ws[k4+1][r] = vw.y;
            Ws[k4+2][r] = vw.z; Ws[k4+3][r] = vw.w;
        }
        __syncthreads();
        #pragma unroll
        for (int k = 0; k < 16; k++) {
            float a0 = As[ty*4+0][k];
            float a1 = As[ty*4+1][k];
            float a2 = As[ty*4+2][k];
            float a3 = As[ty*4+3][k];
            float4 w = *(const float4*)&Ws[k][tx*4];
            c[0][0] += a0*w.x; c[0][1] += a0*w.y; c[0][2] += a0*w.z; c[0][3] += a0*w.w;
            c[1][0] += a1*w.x; c[1][1] += a1*w.y; c[1][2] += a1*w.z; c[1][3] += a1*w.w;
            c[2][0] += a2*w.x; c[2][1] += a2*w.y; c[2][2] += a2*w.z; c[2][3] += a2*w.w;
            c[3][0] += a3*w.x; c[3][1] += a3*w.y; c[3][2] += a3*w.z; c[3][3] += a3*w.w;
        }
        __syncthreads();
    }

    // Epilogue: add Vb + Wb, store to g_pre
    const int nbase = bn*64 + tx*4;
    float bx = Vb[nbase+0] + Wb[nbase+0];
    float by = Vb[nbase+1] + Wb[nbase+1];
    float bz = Vb[nbase+2] + Wb[nbase+2];
    float bw = Vb[nbase+3] + Wb[nbase+3];
    #pragma unroll
    for (int i = 0; i < 4; i++) {
        size_t row = (size_t)bm*64 + ty*4 + i;
        float4 o = make_float4(c[i][0]+bx, c[i][1]+by, c[i][2]+bz, c[i][3]+bw);
        *(float4*)&g_pre[row*HH + nbase] = o;
    }
}

// =================================================================================
// Kernel 2: persistent recurrence.
//   Each block (nt, kc) keeps Ww[nt*64 .. +63][kc*128 .. +127] in SMEM for all steps.
//   Per step: phase A  -> partial[kc][b][n] = sum_{k in chunk} h[b,k]*Ww[n,k]
//             barrier
//             phase B  -> h_t = tanh(sum_kc partial + g_pre[t])  -> d_out slice t
//             barrier
// =================================================================================
__global__ void __launch_bounds__(256) rnn_recurrent_kernel(
        const float* __restrict__ Ww,
        float* __restrict__ out) {
    extern __shared__ float smem[];
    float (*Ws)[64]  = (float(*)[64])smem;               // [k=128][n=64]  32 KB
    float (*As)[132] = (float(*)[132])(smem + 128*64);   // [b=64][k pad]  33.8 KB

    const int bid = blockIdx.x;
    const int nt  = bid & (NT-1);      // 0..15
    const int kc  = bid >> 4;          // 0..7
    const int t   = threadIdx.x;
    const int tx  = t & 15;            // n micro
    const int ty  = t >> 4;            // b micro

    // Preload resident Ww slice, transposed to [k][n]
    for (int q = t; q < 64*32; q += 256) {     // float4 units
        int n  = q >> 5;                       // 0..63
        int kq = q & 31;                       // 0..31
        float4 v = *(const float4*)(Ww + (size_t)(nt*64 + n)*HH + kc*128 + kq*4);
        Ws[kq*4+0][n] = v.x; Ws[kq*4+1][n] = v.y;
        Ws[kq*4+2][n] = v.z; Ws[kq*4+3][n] = v.w;
    }
    __syncthreads();

    for (int step = 0; step < SS; step++) {
        if (step > 0) {
            const float* hprev = out + (size_t)(step-1)*BH;
            // Stage h chunk [64 x 128] into SMEM (L2 path: written by other SMs)
            for (int q = t; q < 64*32; q += 256) {
                int b  = q >> 5;
                int kq = q & 31;
                float4 v = __ldcg((const float4*)(hprev + (size_t)b*HH + kc*128 + kq*4));
                *(float4*)&As[b][kq*4] = v;
            }
            __syncthreads();

            float c[4][4] = {};
            #pragma unroll 8
            for (int k = 0; k < 128; k++) {
                float a0 = As[ty*4+0][k];
                float a1 = As[ty*4+1][k];
                float a2 = As[ty*4+2][k];
                float a3 = As[ty*4+3][k];
                float4 w = *(const float4*)&Ws[k][tx*4];
                c[0][0] += a0*w.x; c[0][1] += a0*w.y; c[0][2] += a0*w.z; c[0][3] += a0*w.w;
                c[1][0] += a1*w.x; c[1][1] += a1*w.y; c[1][2] += a1*w.z; c[1][3] += a1*w.w;
                c[2][0] += a2*w.x; c[2][1] += a2*w.y; c[2][2] += a2*w.z; c[2][3] += a2*w.w;
                c[3][0] += a3*w.x; c[3][1] += a3*w.y; c[3][2] += a3*w.z; c[3][3] += a3*w.w;
            }
            // Store partials
            #pragma unroll
            for (int i = 0; i < 4; i++) {
                float4 v = make_float4(c[i][0], c[i][1], c[i][2], c[i][3]);
                *(float4*)&g_part[kc][(size_t)(ty*4+i)*HH + nt*64 + tx*4] = v;
            }
            __syncthreads();   // As fully consumed before next overwrite
        }
        grid_sync_128();

        // Phase B: reduce 8 partials + pre, tanh, write h_t
        {
            float* hout = out + (size_t)step*BH;
            const float* pre = g_pre + (size_t)step*BH;
            for (int o = bid*256 + t; o < BH; o += NB*256) {
                float acc = pre[o];
                if (step > 0) {
                    #pragma unroll
                    for (int kk = 0; kk < KC; kk++)
                        acc += __ldcg(&g_part[kk][o]);
                }
                hout[o] = tanhf(acc);
            }
        }
        grid_sync_128();
    }

    // h_final copy: d_out[S*BH ..] = last hidden state
    for (int o = bid*256 + t; o < BH; o += NB*256) {
        out[(size_t)SS*BH + o] = __ldcg(&out[(size_t)(SS-1)*BH + o]);
    }
}

// =================================================================================
// Launch
// =================================================================================
extern "C" void kernel_launch(void* const* d_in, const int* in_sizes, int n_in,
                              void* d_out, int out_size) {
    const float* x  = (const float*)d_in[0];   // (S,B,I)
    const float* Ww = (const float*)d_in[1];   // (H,H)
    const float* Wb = (const float*)d_in[2];   // (H)
    const float* Vw = (const float*)d_in[3];   // (H,I)
    const float* Vb = (const float*)d_in[4];   // (H)
    float* out = (float*)d_out;                // (S,B,H) then (1,B,H)

    // Kernel 1: input projection + fused biases
    dim3 g1(512, 16);
    pre_gemm_kernel<<<g1, 256>>>(x, Vw, Wb, Vb);

    // Kernel 2: persistent recurrence (dynamic SMEM > 48KB static limit)
    static int smem_set = 0;
    const int smem_bytes = (128*64 + 64*132) * (int)sizeof(float);  // 66560
    if (!smem_set) {
        cudaFuncSetAttribute(rnn_recurrent_kernel,
                             cudaFuncAttributeMaxDynamicSharedMemorySize, smem_bytes);
        smem_set = 1;
    }
    rnn_recurrent_kernel<<<NB, 256, smem_bytes>>>(Ww, out);
}

// round 2
// speedup vs baseline: 1.0163x; 1.0163x over previous
#include <cuda_runtime.h>
#include <math.h>

// Problem dims
#define SS 512
#define BB 64
#define II 512
#define HH 1024
#define BH (BB*HH)

// Recurrent kernel decomposition: 8 n-tiles (128 cols) x 16 k-chunks (64 k) = 128 blocks
#define NT 8
#define KC 16
#define NB (NT*KC)     // 128 persistent blocks (<= 148 SMs -> single wave)

// -------------------- device scratch (no cudaMalloc allowed) --------------------
__device__ float g_pre[SS*BH];        // V x_t + b_V + b_W, precomputed
__device__ float g_part[KC][BH];      // split-K partial sums per step (4 MB)
__device__ unsigned g_bar_cnt = 0;
__device__ volatile unsigned g_bar_gen = 0;

// -------------------- packed f32x2 helpers (FFMA2: 2x fp32 throughput) ----------
typedef unsigned long long u64;

__device__ __forceinline__ u64 pack2(float x, float y) {
    u64 r; asm("mov.b64 %0, {%1, %2};" : "=l"(r) : "f"(x), "f"(y)); return r;
}
__device__ __forceinline__ u64 fma2(u64 a, u64 b, u64 c) {
    u64 d; asm("fma.rn.f32x2 %0, %1, %2, %3;" : "=l"(d) : "l"(a), "l"(b), "l"(c));
    return d;
}
__device__ __forceinline__ float2 unpack2(u64 v) {
    float2 f; asm("mov.b64 {%0, %1}, %2;" : "=f"(f.x), "=f"(f.y) : "l"(v)); return f;
}

// -------------------- software grid barrier (sense via generation) --------------
__device__ __forceinline__ void grid_sync_128() {
    __syncthreads();
    __threadfence();                       // publish our STGs to L2 before arrival
    if (threadIdx.x == 0) {
        unsigned gen = g_bar_gen;
        unsigned ticket = atomicAdd(&g_bar_cnt, 1u);
        if (ticket == NB - 1u) {
            g_bar_cnt = 0;                 // reset BEFORE releasing
            __threadfence();
            g_bar_gen = gen + 1u;          // release
        } else {
            while (g_bar_gen == gen) { }   // spin (volatile load)
        }
    }
    __syncthreads();
}

// =================================================================================
// Kernel 1: g_pre[s,b,h] = sum_i x[s,b,i]*Vw[h,i] + Vb[h] + Wb[h]
// M = S*B = 32768, N = H = 1024, K = I = 512.
// Tile 128x128, BK=16, 256 threads, 8x8 micro with f32x2 (crossbar-balanced).
// =================================================================================
__global__ void __launch_bounds__(256) pre_gemm_kernel(
        const float* __restrict__ x,
        const float* __restrict__ Vw,
        const float* __restrict__ Wb,
        const float* __restrict__ Vb) {
    __shared__ float As[128][20];   // [m][k] pad to 20 (80B rows, 16B-aligned)
    __shared__ float Ws[16][132];   // [k][n] pad to 132 (528B rows, 16B-aligned)

    const int bm = blockIdx.x;     // 0..255
    const int bn = blockIdx.y;     // 0..7
    const int t  = threadIdx.x;
    const int tx = t & 15;         // n group: 16 groups x 8 cols
    const int ty = t >> 4;         // m group: 16 groups x 8 rows

    u64 acc[8][4];
    #pragma unroll
    for (int j = 0; j < 8; j++)
        #pragma unroll
        for (int p = 0; p < 4; p++) acc[j][p] = 0ull;   // bit pattern 0 == 0.0f pair

    const float* Arow = x  + (size_t)(bm*128) * II;
    const float* Wrow = Vw + (size_t)(bn*128) * II;

    for (int kb = 0; kb < II; kb += 16) {
        // Load A tile 128x16 and W tile 128x16 (2 float4 each per thread)
        #pragma unroll
        for (int it = 0; it < 2; it++) {
            int q  = t + it*256;
            int r  = q >> 2;               // 0..127
            int k4 = (q & 3) << 2;         // 0,4,8,12
            float4 va = *(const float4*)(Arow + (size_t)r*II + kb + k4);
            *(float4*)&As[r][k4] = va;
            float4 vw = *(const float4*)(Wrow + (size_t)r*II + kb + k4);
            Ws[k4+0][r] = vw.x; Ws[k4+1][r] = vw.y;
            Ws[k4+2][r] = vw.z; Ws[k4+3][r] = vw.w;
        }
        __syncthreads();
        #pragma unroll
        for (int k = 0; k < 16; k++) {
            ulonglong2 w01 = *(const ulonglong2*)&Ws[k][tx*8];
            ulonglong2 w23 = *(const ulonglong2*)&Ws[k][tx*8 + 4];
            #pragma unroll
            for (int j = 0; j < 8; j++) {
                float a = As[ty*8 + j][k];       // warp broadcast (2 addrs/warp)
                u64 ap = pack2(a, a);
                acc[j][0] = fma2(ap, w01.x, acc[j][0]);
                acc[j][1] = fma2(ap, w01.y, acc[j][1]);
                acc[j][2] = fma2(ap, w23.x, acc[j][2]);
                acc[j][3] = fma2(ap, w23.y, acc[j][3]);
            }
        }
        __syncthreads();
    }

    // Epilogue: add Vb + Wb, store to g_pre
    const int nbase = bn*128 + tx*8;
    float bias[8];
    #pragma unroll
    for (int i = 0; i < 8; i++) bias[i] = Vb[nbase+i] + Wb[nbase+i];

    #pragma unroll
    for (int j = 0; j < 8; j++) {
        size_t row = (size_t)bm*128 + ty*8 + j;
        float2 c0 = unpack2(acc[j][0]);
        float2 c1 = unpack2(acc[j][1]);
        float2 c2 = unpack2(acc[j][2]);
        float2 c3 = unpack2(acc[j][3]);
        float4 o0 = make_float4(c0.x+bias[0], c0.y+bias[1], c1.x+bias[2], c1.y+bias[3]);
        float4 o1 = make_float4(c2.x+bias[4], c2.y+bias[5], c3.x+bias[6], c3.y+bias[7]);
        *(float4*)&g_pre[row*HH + nbase]     = o0;
        *(float4*)&g_pre[row*HH + nbase + 4] = o1;
    }
}

// =================================================================================
// Kernel 2: persistent recurrence.
//   Block (nt, kc) keeps Ww[nt*128 .. +127][kc*64 .. +63] in SMEM for all steps.
//   Per step: phase A  -> partial[kc][b][n] = sum_{k in chunk} h[b,k]*Ww[n,k]
//             barrier
//             phase B  -> h_t = tanh(sum_kc partial + g_pre[t])  -> d_out slice t
//             barrier
// 128 threads, 8(b)x8(n) micro with f32x2.
// =================================================================================
__global__ void __launch_bounds__(128) rnn_recurrent_kernel(
        const float* __restrict__ Ww,
        float* __restrict__ out) {
    extern __shared__ float smem[];
    float (*Ws)[132] = (float(*)[132])smem;               // [k=64][n=128+4]  33.8 KB
    float (*As)[68]  = (float(*)[68])(smem + 64*132);     // [b=64][k=64+4]   17.4 KB

    const int bid = blockIdx.x;
    const int nt  = bid & (NT-1);      // 0..7
    const int kc  = bid >> 3;          // 0..15
    const int t   = threadIdx.x;
    const int tx  = t & 15;            // n group: 16 x 8 = 128 cols
    const int ty  = t >> 4;            // b group:  8 x 8 =  64 rows

    // Preload resident Ww slice, transposed to [k][n]
    for (int q = t; q < 128*16; q += 128) {    // float4 units: 128 n x 16 k4
        int n  = q >> 4;                       // 0..127
        int k4 = (q & 15) << 2;                // 0,4,...,60
        float4 v = *(const float4*)(Ww + (size_t)(nt*128 + n)*HH + kc*64 + k4);
        Ws[k4+0][n] = v.x; Ws[k4+1][n] = v.y;
        Ws[k4+2][n] = v.z; Ws[k4+3][n] = v.w;
    }
    __syncthreads();

    for (int step = 0; step < SS; step++) {
        if (step > 0) {
            const float* hprev = out + (size_t)(step-1)*BH;
            // Stage h chunk [64 x 64] into SMEM (L2 path: written by other SMs)
            for (int q = t; q < 64*16; q += 128) {
                int b  = q >> 4;
                int k4 = (q & 15) << 2;
                float4 v = __ldcg((const float4*)(hprev + (size_t)b*HH + kc*64 + k4));
                *(float4*)&As[b][k4] = v;
            }
            __syncthreads();

            u64 acc[8][4];
            #pragma unroll
            for (int j = 0; j < 8; j++)
                #pragma unroll
                for (int p = 0; p < 4; p++) acc[j][p] = 0ull;

            #pragma unroll 8
            for (int k = 0; k < 64; k++) {
                ulonglong2 w01 = *(const ulonglong2*)&Ws[k][tx*8];
                ulonglong2 w23 = *(const ulonglong2*)&Ws[k][tx*8 + 4];
                #pragma unroll
                for (int j = 0; j < 8; j++) {
                    float a = As[ty*8 + j][k];
                    u64 ap = pack2(a, a);
                    acc[j][0] = fma2(ap, w01.x, acc[j][0]);
                    acc[j][1] = fma2(ap, w01.y, acc[j][1]);
                    acc[j][2] = fma2(ap, w23.x, acc[j][2]);
                    acc[j][3] = fma2(ap, w23.y, acc[j][3]);
                }
            }
            // Store partials (each u64 pair is 2 adjacent n-values -> 16B stores)
            #pragma unroll
            for (int j = 0; j < 8; j++) {
                float* dst = &g_part[kc][(size_t)(ty*8 + j)*HH + nt*128 + tx*8];
                ulonglong2 v0; v0.x = acc[j][0]; v0.y = acc[j][1];
                ulonglong2 v1; v1.x = acc[j][2]; v1.y = acc[j][3];
                *(ulonglong2*)(dst)     = v0;
                *(ulonglong2*)(dst + 4) = v1;
            }
        }
        grid_sync_128();

        // Phase B: reduce 16 partials + pre, tanh, write h_t.
        // Exactly one float4 per thread: 128 blocks * 128 thr * 4 = 65536 = BH.
        {
            const int o = (bid*128 + t) * 4;
            float4 a4 = *(const float4*)&g_pre[(size_t)step*BH + o];
            if (step > 0) {
                #pragma unroll
                for (int kk = 0; kk < KC; kk++) {
                    float4 p = __ldcg((const float4*)&g_part[kk][o]);
                    a4.x += p.x; a4.y += p.y; a4.z += p.z; a4.w += p.w;
                }
            }
            float4 h4 = make_float4(tanhf(a4.x), tanhf(a4.y), tanhf(a4.z), tanhf(a4.w));
            *(float4*)&out[(size_t)step*BH + o] = h4;
        }
        grid_sync_128();
    }

    // h_final copy: d_out[S*BH ..] = last hidden state
    {
        const int o = (bid*128 + t) * 4;
        float4 v = __ldcg((const float4*)&out[(size_t)(SS-1)*BH + o]);
        *(float4*)&out[(size_t)SS*BH + o] = v;
    }
}

// =================================================================================
// Launch
// =================================================================================
extern "C" void kernel_launch(void* const* d_in, const int* in_sizes, int n_in,
                              void* d_out, int out_size) {
    const float* x  = (const float*)d_in[0];   // (S,B,I)
    const float* Ww = (const float*)d_in[1];   // (H,H)
    const float* Wb = (const float*)d_in[2];   // (H)
    const float* Vw = (const float*)d_in[3];   // (H,I)
    const float* Vb = (const float*)d_in[4];   // (H)
    float* out = (float*)d_out;                // (S,B,H) then (1,B,H)

    // Kernel 1: input projection + fused biases
    dim3 g1(256, 8);
    pre_gemm_kernel<<<g1, 256>>>(x, Vw, Wb, Vb);

    // Kernel 2: persistent recurrence (dynamic SMEM > 48KB static limit)
    static int smem_set = 0;
    const int smem_bytes = (64*132 + 64*68) * (int)sizeof(float);  // 51200
    if (!smem_set) {
        cudaFuncSetAttribute(rnn_recurrent_kernel,
                             cudaFuncAttributeMaxDynamicSharedMemorySize, smem_bytes);
        smem_set = 1;
    }
    rnn_recurrent_kernel<<<NB, 128, smem_bytes>>>(Ww, out);
}